// round 2
// baseline (speedup 1.0000x reference)
#include <cuda_runtime.h>
#include <cuda_bf16.h>

#define H 128
#define N_USER_MAX 100000
#define N_ITEM_MAX 50000

// Scratch: precomputed projections (77 MB total, static device globals per harness rules)
__device__ float g_p_user[(size_t)N_USER_MAX * H];
__device__ float g_p_item[(size_t)N_ITEM_MAX * H];

// ---------------------------------------------------------------------------
// Precompute kernel: P[r, :] = Z[r, :] @ W (+ bias)
//   Z: [nrows, 128], W: [128, 128] row-major, P: [nrows, 128]
// Block: 256 threads, tile 64 rows x 128 cols.
// Thread (ty, tx): ty = tid/16 -> 4 rows, tx = tid%16 -> 8 cols. 32 accum regs.
// A tile staged in smem (padded to kill LDS.128 bank conflicts); W streamed
// via L1 (full W = 64 KB, stays resident).
// ---------------------------------------------------------------------------
__global__ __launch_bounds__(256) void precompute_kernel(
    const float* __restrict__ Z, const float* __restrict__ W,
    const float* __restrict__ bias, int nrows, int which)
{
    __shared__ float sA[64][H + 4];   // +4 pad: ty-groups hit distinct banks
    float* P = which ? g_p_item : g_p_user;

    const int row0 = blockIdx.x * 64;
    int rows_here = nrows - row0;
    if (rows_here > 64) rows_here = 64;
    const int tid = threadIdx.x;

    // Stage A tile: rows_here x 128 floats, coalesced float4 loads
    for (int i = tid; i < rows_here * (H / 4); i += 256) {
        int r  = i >> 5;       // i / 32 float4s per row
        int c4 = i & 31;
        float4 v = reinterpret_cast<const float4*>(Z + (size_t)(row0 + r) * H)[c4];
        *reinterpret_cast<float4*>(&sA[r][c4 * 4]) = v;
    }
    __syncthreads();

    const int tx = tid & 15;   // col group: cols [tx*8, tx*8+8)
    const int ty = tid >> 4;   // row group: rows [ty*4, ty*4+4)

    float acc[4][8];
#pragma unroll
    for (int r = 0; r < 4; r++)
#pragma unroll
        for (int c = 0; c < 8; c++) acc[r][c] = 0.f;

    const float* Wp = W + tx * 8;

    for (int k0 = 0; k0 < H; k0 += 4) {
        float4 a[4];
#pragma unroll
        for (int r = 0; r < 4; r++)
            a[r] = *reinterpret_cast<const float4*>(&sA[ty * 4 + r][k0]);
#pragma unroll
        for (int kk = 0; kk < 4; kk++) {
            float4 w0 = *reinterpret_cast<const float4*>(Wp + (size_t)(k0 + kk) * H);
            float4 w1 = *reinterpret_cast<const float4*>(Wp + (size_t)(k0 + kk) * H + 4);
            float wv[8] = {w0.x, w0.y, w0.z, w0.w, w1.x, w1.y, w1.z, w1.w};
            float av[4];
#pragma unroll
            for (int r = 0; r < 4; r++)
                av[r] = (kk == 0) ? a[r].x : (kk == 1) ? a[r].y : (kk == 2) ? a[r].z : a[r].w;
#pragma unroll
            for (int r = 0; r < 4; r++)
#pragma unroll
                for (int c = 0; c < 8; c++)
                    acc[r][c] = fmaf(av[r], wv[c], acc[r][c]);
        }
    }

    // Optional bias (b1 folded into p_user only)
    if (bias != nullptr) {
#pragma unroll
        for (int c = 0; c < 8; c++) {
            float b = bias[tx * 8 + c];
#pragma unroll
            for (int r = 0; r < 4; r++) acc[r][c] += b;
        }
    }

    // Store: two float4 per row, coalesced
#pragma unroll
    for (int r = 0; r < 4; r++) {
        int rr = ty * 4 + r;
        if (rr < rows_here) {
            float4 o0 = {acc[r][0], acc[r][1], acc[r][2], acc[r][3]};
            float4 o1 = {acc[r][4], acc[r][5], acc[r][6], acc[r][7]};
            float4* dst = reinterpret_cast<float4*>(P + (size_t)(row0 + rr) * H + tx * 8);
            dst[0] = o0;
            dst[1] = o1;
        }
    }
}

// ---------------------------------------------------------------------------
// Edge kernel: one warp per edge.
//   out[e] = sum_c relu(p_user[row[e]][c] + p_item[col[e]][c]) * W2[c] + b2
// Each lane handles 4 contiguous channels (float4) -> perfectly coalesced
// 512 B row reads, then butterfly reduce.
// ---------------------------------------------------------------------------
__global__ __launch_bounds__(256) void edge_kernel(
    const int* __restrict__ row, const int* __restrict__ col,
    const float* __restrict__ W2, const float* __restrict__ b2,
    float* __restrict__ out, int E)
{
    const int warp_id = (int)((blockIdx.x * 256u + threadIdx.x) >> 5);
    const int lane = threadIdx.x & 31;
    if (warp_id >= E) return;

    const int u = __ldg(row + warp_id);   // uniform across warp -> broadcast
    const int v = __ldg(col + warp_id);

    float4 pu = reinterpret_cast<const float4*>(g_p_user + (size_t)u * H)[lane];
    float4 pi = reinterpret_cast<const float4*>(g_p_item + (size_t)v * H)[lane];
    float4 w  = reinterpret_cast<const float4*>(W2)[lane];

    float s = fmaf(fmaxf(pu.x + pi.x, 0.f), w.x,
              fmaf(fmaxf(pu.y + pi.y, 0.f), w.y,
              fmaf(fmaxf(pu.z + pi.z, 0.f), w.z,
                   fmaxf(pu.w + pi.w, 0.f) * w.w)));

#pragma unroll
    for (int off = 16; off; off >>= 1)
        s += __shfl_xor_sync(0xFFFFFFFFu, s, off);

    if (lane == 0) out[warp_id] = s + __ldg(b2);
}

// ---------------------------------------------------------------------------
// Launch: inputs per metadata order:
//   z_user f32 [100000,128], z_item f32 [50000,128], row i32 [1M], col i32 [1M],
//   W1 f32 [256,128], b1 f32 [128], W2 f32 [128,1], b2 f32 [1] -> out f32 [1M]
// ---------------------------------------------------------------------------
extern "C" void kernel_launch(void* const* d_in, const int* in_sizes, int n_in,
                              void* d_out, int out_size)
{
    const float* z_user = (const float*)d_in[0];
    const float* z_item = (const float*)d_in[1];
    const int*   row    = (const int*)d_in[2];
    const int*   col    = (const int*)d_in[3];
    const float* W1     = (const float*)d_in[4];
    const float* b1     = (const float*)d_in[5];
    const float* W2     = (const float*)d_in[6];
    const float* b2     = (const float*)d_in[7];
    float* out = (float*)d_out;

    const int n_user = in_sizes[0] / H;
    const int n_item = in_sizes[1] / H;
    const int E      = in_sizes[2];

    // p_user = z_user @ W1[:128] + b1 ; p_item = z_item @ W1[128:]
    precompute_kernel<<<(n_user + 63) / 64, 256>>>(z_user, W1, b1, n_user, 0);
    precompute_kernel<<<(n_item + 63) / 64, 256>>>(z_item, W1 + H * H, nullptr, n_item, 1);

    // Edge phase: warp per edge, 8 warps per block
    edge_kernel<<<(E + 7) / 8, 256>>>(row, col, W2, b2, out, E);
}

// round 5
// speedup vs baseline: 1.7299x; 1.7299x over previous
#include <cuda_runtime.h>
#include <cuda_fp16.h>

#define H 128
#define N_USER_MAX 100000
#define N_ITEM_MAX 50000

// Scratch: precomputed projections stored as fp16 (halves gather traffic).
// Values ~N(0, 0.7^2) -> fp16 rounding eps 2.4e-4 -> final rel-err ~4e-4 < 1e-3.
__device__ __half g_p_user[(size_t)N_USER_MAX * H];
__device__ __half g_p_item[(size_t)N_ITEM_MAX * H];

// ---------------------------------------------------------------------------
// Fused precompute: one launch covers both tables.
//   blocks [0, nb_user)             : p_user = z_user @ W1[:128] + b1
//   blocks [nb_user, nb_user+nb_it) : p_item = z_item @ W1[128:]
// Tile: 64 rows x 128 cols per 128-thread block; 8x8 per thread.
// smem: 64*(128+4)*4 = 33.8 KB (under the 48 KB static cap).
// Per 4-k chunk: 8 LDS.128 (A) + 8 LDG.128 (W, 64 KB L1-resident) per 256 FFMA.
// ---------------------------------------------------------------------------
__global__ __launch_bounds__(128) void precompute_fused(
    const float* __restrict__ z_user, const float* __restrict__ z_item,
    const float* __restrict__ W1, const float* __restrict__ b1,
    int n_user, int n_item, int nb_user)
{
    __shared__ float sA[64][H + 4];

    const bool is_user = (int)blockIdx.x < nb_user;
    const float* Z;
    const float* W;
    __half* P;
    int nrows, row0;
    if (is_user) {
        Z = z_user; W = W1;          P = g_p_user; nrows = n_user;
        row0 = blockIdx.x * 64;
    } else {
        Z = z_item; W = W1 + H * H;  P = g_p_item; nrows = n_item;
        row0 = (blockIdx.x - nb_user) * 64;
    }
    int rows_here = nrows - row0;
    if (rows_here > 64) rows_here = 64;

    const int tid = threadIdx.x;

    // Stage A tile (coalesced float4): 64 rows x 32 float4
    for (int i = tid; i < rows_here * (H / 4); i += 128) {
        int r  = i >> 5;
        int c4 = i & 31;
        float4 v = reinterpret_cast<const float4*>(Z + (size_t)(row0 + r) * H)[c4];
        *reinterpret_cast<float4*>(&sA[r][c4 * 4]) = v;
    }
    __syncthreads();

    const int tx = tid & 15;   // cols [tx*8, tx*8+8)
    const int ty = tid >> 4;   // rows [ty*8, ty*8+8)

    float acc[8][8];
#pragma unroll
    for (int r = 0; r < 8; r++)
#pragma unroll
        for (int c = 0; c < 8; c++) acc[r][c] = 0.f;

    const float* Wp = W + tx * 8;

    for (int k0 = 0; k0 < H; k0 += 4) {
        float4 a[8];
#pragma unroll
        for (int r = 0; r < 8; r++)
            a[r] = *reinterpret_cast<const float4*>(&sA[ty * 8 + r][k0]);
#pragma unroll
        for (int kk = 0; kk < 4; kk++) {
            float4 w0 = __ldg(reinterpret_cast<const float4*>(Wp + (size_t)(k0 + kk) * H));
            float4 w1 = __ldg(reinterpret_cast<const float4*>(Wp + (size_t)(k0 + kk) * H + 4));
            float wv[8] = {w0.x, w0.y, w0.z, w0.w, w1.x, w1.y, w1.z, w1.w};
            float av[8];
#pragma unroll
            for (int r = 0; r < 8; r++)
                av[r] = (kk == 0) ? a[r].x : (kk == 1) ? a[r].y : (kk == 2) ? a[r].z : a[r].w;
#pragma unroll
            for (int r = 0; r < 8; r++)
#pragma unroll
                for (int c = 0; c < 8; c++)
                    acc[r][c] = fmaf(av[r], wv[c], acc[r][c]);
        }
    }

    if (is_user) {
#pragma unroll
        for (int c = 0; c < 8; c++) {
            float b = __ldg(b1 + tx * 8 + c);
#pragma unroll
            for (int r = 0; r < 8; r++) acc[r][c] += b;
        }
    }

    // Store as fp16: 8 cols -> 4 half2 -> one uint4 per row
#pragma unroll
    for (int r = 0; r < 8; r++) {
        int rr = ty * 8 + r;
        if (rr < rows_here) {
            __half2 h[4];
#pragma unroll
            for (int j = 0; j < 4; j++)
                h[j] = __floats2half2_rn(acc[r][2 * j], acc[r][2 * j + 1]);
            *reinterpret_cast<uint4*>(P + (size_t)(row0 + rr) * H + tx * 8) =
                *reinterpret_cast<uint4*>(h);
        }
    }
}

// ---------------------------------------------------------------------------
// Edge kernel: 8 lanes per edge, 4 edges per warp-iteration, grid-stride.
//   out[e] = sum_c relu(pu[row[e]][c] + pi[col[e]][c]) * W2[c] + b2
// Each lane loads 2x uint4 (16 halves = 32 B) per table -> 256 B coalesced row.
// W2 hoisted into registers; 8 LDG.128 in flight per warp-iteration.
// ---------------------------------------------------------------------------
__global__ __launch_bounds__(256) void edge_kernel(
    const int* __restrict__ row, const int* __restrict__ col,
    const float* __restrict__ W2, const float* __restrict__ b2,
    float* __restrict__ out, int E)
{
    const int lane = threadIdx.x & 31;
    const int sub  = lane >> 3;   // edge slot 0..3 within warp
    const int l    = lane & 7;    // lane within edge: halves [l*16, l*16+16)

    float w2v[16];
#pragma unroll
    for (int i = 0; i < 16; i++) w2v[i] = __ldg(W2 + l * 16 + i);
    const float b2v = __ldg(b2);

    const int warp_global = (int)((blockIdx.x * 256u + threadIdx.x) >> 5);
    const int total_warps = (int)((gridDim.x * 256u) >> 5);

    for (int e = warp_global * 4 + sub; e < E; e += total_warps * 4) {
        const int u = __ldg(row + e);
        const int v = __ldg(col + e);

        const uint4* pu = reinterpret_cast<const uint4*>(g_p_user + (size_t)u * H) + l * 2;
        const uint4* pi = reinterpret_cast<const uint4*>(g_p_item + (size_t)v * H) + l * 2;
        uint4 a0 = pu[0];
        uint4 a1 = pu[1];
        uint4 c0 = pi[0];
        uint4 c1 = pi[1];

        const __half2* A0 = reinterpret_cast<const __half2*>(&a0);
        const __half2* A1 = reinterpret_cast<const __half2*>(&a1);
        const __half2* C0 = reinterpret_cast<const __half2*>(&c0);
        const __half2* C1 = reinterpret_cast<const __half2*>(&c1);

        float s = 0.f;
#pragma unroll
        for (int j = 0; j < 4; j++) {
            float2 fa = __half22float2(A0[j]);
            float2 fb = __half22float2(C0[j]);
            s = fmaf(fmaxf(fa.x + fb.x, 0.f), w2v[2 * j],     s);
            s = fmaf(fmaxf(fa.y + fb.y, 0.f), w2v[2 * j + 1], s);
        }
#pragma unroll
        for (int j = 0; j < 4; j++) {
            float2 fa = __half22float2(A1[j]);
            float2 fb = __half22float2(C1[j]);
            s = fmaf(fmaxf(fa.x + fb.x, 0.f), w2v[8 + 2 * j],     s);
            s = fmaf(fmaxf(fa.y + fb.y, 0.f), w2v[8 + 2 * j + 1], s);
        }

        // Reduce across the 8 lanes of this edge group
#pragma unroll
        for (int off = 4; off; off >>= 1)
            s += __shfl_xor_sync(0xFFFFFFFFu, s, off);

        if (l == 0) out[e] = s + b2v;
    }
}

// ---------------------------------------------------------------------------
// Inputs (metadata order): z_user f32[100000*128], z_item f32[50000*128],
//   row i32[E], col i32[E], W1 f32[256*128], b1 f32[128], W2 f32[128], b2 f32[1]
// Output: f32[E]
// ---------------------------------------------------------------------------
extern "C" void kernel_launch(void* const* d_in, const int* in_sizes, int n_in,
                              void* d_out, int out_size)
{
    const float* z_user = (const float*)d_in[0];
    const float* z_item = (const float*)d_in[1];
    const int*   row    = (const int*)d_in[2];
    const int*   col    = (const int*)d_in[3];
    const float* W1     = (const float*)d_in[4];
    const float* b1     = (const float*)d_in[5];
    const float* W2     = (const float*)d_in[6];
    const float* b2     = (const float*)d_in[7];
    float* out = (float*)d_out;

    const int n_user = in_sizes[0] / H;
    const int n_item = in_sizes[1] / H;
    const int E      = in_sizes[2];

    const int nb_user = (n_user + 63) / 64;
    const int nb_item = (n_item + 63) / 64;

    precompute_fused<<<nb_user + nb_item, 128>>>(z_user, z_item, W1, b1,
                                                 n_user, n_item, nb_user);

    edge_kernel<<<1184, 256>>>(row, col, W2, b2, out, E);
}

// round 6
// speedup vs baseline: 2.1012x; 1.2147x over previous
#include <cuda_runtime.h>
#include <cuda_fp16.h>

#define H 128
#define N_USER_MAX 100000
#define N_ITEM_MAX 50000

// Precomputed projections stored as fp16 (halves gather traffic).
__device__ __half g_p_user[(size_t)N_USER_MAX * H];
__device__ __half g_p_item[(size_t)N_ITEM_MAX * H];

// ---- Packed fp32 (FFMA2) helpers: 2x fp32 FMA per instruction, full precision.
__device__ __forceinline__ unsigned long long pack2(float lo, float hi) {
    unsigned long long r;
    asm("mov.b64 %0, {%1, %2};" : "=l"(r) : "f"(lo), "f"(hi));
    return r;
}
__device__ __forceinline__ void ffma2(unsigned long long& d,
                                      unsigned long long a,
                                      unsigned long long b) {
    asm("fma.rn.f32x2 %0, %1, %2, %0;" : "+l"(d) : "l"(a), "l"(b));
}
__device__ __forceinline__ float2 unpack2(unsigned long long v) {
    float2 f;
    asm("mov.b64 {%0, %1}, %2;" : "=f"(f.x), "=f"(f.y) : "l"(v));
    return f;
}

// ---------------------------------------------------------------------------
// Fused precompute: one launch covers both tables.
//   blocks [0, nb_user)             : p_user = z_user @ W1[:128] + b1
//   blocks [nb_user, nb_user+nb_it) : p_item = z_item @ W1[128:]
// Tile: 64 rows x 128 cols per 128-thread block; 8 rows x 4 col-pairs per
// thread, accumulated in packed f32x2 (FFMA2). Per kk: 32 FFMA2 (64 FMA) +
// 2 LDG.128 (W, L1-resident) + 8 pack movs (alu pipe, overlapped).
// smem: 64*(128+4)*4 = 33.8 KB (under the 48 KB static cap).
// ---------------------------------------------------------------------------
__global__ __launch_bounds__(128) void precompute_fused(
    const float* __restrict__ z_user, const float* __restrict__ z_item,
    const float* __restrict__ W1, const float* __restrict__ b1,
    int n_user, int n_item, int nb_user)
{
    __shared__ float sA[64][H + 4];

    const bool is_user = (int)blockIdx.x < nb_user;
    const float* Z;
    const float* W;
    __half* P;
    int nrows, row0;
    if (is_user) {
        Z = z_user; W = W1;          P = g_p_user; nrows = n_user;
        row0 = blockIdx.x * 64;
    } else {
        Z = z_item; W = W1 + H * H;  P = g_p_item; nrows = n_item;
        row0 = (blockIdx.x - nb_user) * 64;
    }
    int rows_here = nrows - row0;
    if (rows_here > 64) rows_here = 64;

    const int tid = threadIdx.x;

    // Stage A tile (coalesced float4): 64 rows x 32 float4
    for (int i = tid; i < rows_here * (H / 4); i += 128) {
        int r  = i >> 5;
        int c4 = i & 31;
        float4 v = reinterpret_cast<const float4*>(Z + (size_t)(row0 + r) * H)[c4];
        *reinterpret_cast<float4*>(&sA[r][c4 * 4]) = v;
    }
    __syncthreads();

    const int tx = tid & 15;   // cols [tx*8, tx*8+8) -> 4 packed col-pairs
    const int ty = tid >> 4;   // rows [ty*8, ty*8+8)

    unsigned long long acc2[8][4];
#pragma unroll
    for (int r = 0; r < 8; r++)
#pragma unroll
        for (int c = 0; c < 4; c++) acc2[r][c] = 0ull;   // pair of +0.0f

    const float* Wp = W + tx * 8;

    for (int k0 = 0; k0 < H; k0 += 4) {
        float4 a[8];
#pragma unroll
        for (int r = 0; r < 8; r++)
            a[r] = *reinterpret_cast<const float4*>(&sA[ty * 8 + r][k0]);
#pragma unroll
        for (int kk = 0; kk < 4; kk++) {
            float4 w0 = __ldg(reinterpret_cast<const float4*>(Wp + (size_t)(k0 + kk) * H));
            float4 w1 = __ldg(reinterpret_cast<const float4*>(Wp + (size_t)(k0 + kk) * H + 4));
            unsigned long long ww[4] = {
                pack2(w0.x, w0.y), pack2(w0.z, w0.w),
                pack2(w1.x, w1.y), pack2(w1.z, w1.w)
            };
#pragma unroll
            for (int r = 0; r < 8; r++) {
                float av = (kk == 0) ? a[r].x : (kk == 1) ? a[r].y
                         : (kk == 2) ? a[r].z : a[r].w;
                unsigned long long aa = pack2(av, av);
#pragma unroll
                for (int c = 0; c < 4; c++)
                    ffma2(acc2[r][c], aa, ww[c]);
            }
        }
    }

    // Bias (user table only), then convert col-pairs straight to half2, store.
    float2 bias2[4];
    if (is_user) {
#pragma unroll
        for (int j = 0; j < 4; j++) {
            bias2[j].x = __ldg(b1 + tx * 8 + 2 * j);
            bias2[j].y = __ldg(b1 + tx * 8 + 2 * j + 1);
        }
    }

#pragma unroll
    for (int r = 0; r < 8; r++) {
        int rr = ty * 8 + r;
        if (rr < rows_here) {
            __half2 h[4];
#pragma unroll
            for (int j = 0; j < 4; j++) {
                float2 p = unpack2(acc2[r][j]);
                if (is_user) { p.x += bias2[j].x; p.y += bias2[j].y; }
                h[j] = __floats2half2_rn(p.x, p.y);
            }
            *reinterpret_cast<uint4*>(P + (size_t)(row0 + rr) * H + tx * 8) =
                *reinterpret_cast<uint4*>(h);
        }
    }
}

// ---------------------------------------------------------------------------
// Edge kernel: 8 lanes per edge, 4 edges per warp-iteration, grid-stride.
//   out[e] = sum_c relu(pu[row[e]][c] + pi[col[e]][c]) * W2[c] + b2
// Each lane loads 2x uint4 (16 halves = 32 B) per table -> 256 B coalesced row.
// ---------------------------------------------------------------------------
__global__ __launch_bounds__(256) void edge_kernel(
    const int* __restrict__ row, const int* __restrict__ col,
    const float* __restrict__ W2, const float* __restrict__ b2,
    float* __restrict__ out, int E)
{
    const int lane = threadIdx.x & 31;
    const int sub  = lane >> 3;   // edge slot 0..3 within warp
    const int l    = lane & 7;    // lane within edge: halves [l*16, l*16+16)

    float w2v[16];
#pragma unroll
    for (int i = 0; i < 16; i++) w2v[i] = __ldg(W2 + l * 16 + i);
    const float b2v = __ldg(b2);

    const int warp_global = (int)((blockIdx.x * 256u + threadIdx.x) >> 5);
    const int total_warps = (int)((gridDim.x * 256u) >> 5);

    for (int e = warp_global * 4 + sub; e < E; e += total_warps * 4) {
        const int u = __ldg(row + e);
        const int v = __ldg(col + e);

        const uint4* pu = reinterpret_cast<const uint4*>(g_p_user + (size_t)u * H) + l * 2;
        const uint4* pi = reinterpret_cast<const uint4*>(g_p_item + (size_t)v * H) + l * 2;
        uint4 a0 = pu[0];
        uint4 a1 = pu[1];
        uint4 c0 = pi[0];
        uint4 c1 = pi[1];

        const __half2* A0 = reinterpret_cast<const __half2*>(&a0);
        const __half2* A1 = reinterpret_cast<const __half2*>(&a1);
        const __half2* C0 = reinterpret_cast<const __half2*>(&c0);
        const __half2* C1 = reinterpret_cast<const __half2*>(&c1);

        float s = 0.f;
#pragma unroll
        for (int j = 0; j < 4; j++) {
            float2 fa = __half22float2(A0[j]);
            float2 fb = __half22float2(C0[j]);
            s = fmaf(fmaxf(fa.x + fb.x, 0.f), w2v[2 * j],     s);
            s = fmaf(fmaxf(fa.y + fb.y, 0.f), w2v[2 * j + 1], s);
        }
#pragma unroll
        for (int j = 0; j < 4; j++) {
            float2 fa = __half22float2(A1[j]);
            float2 fb = __half22float2(C1[j]);
            s = fmaf(fmaxf(fa.x + fb.x, 0.f), w2v[8 + 2 * j],     s);
            s = fmaf(fmaxf(fa.y + fb.y, 0.f), w2v[8 + 2 * j + 1], s);
        }

#pragma unroll
        for (int off = 4; off; off >>= 1)
            s += __shfl_xor_sync(0xFFFFFFFFu, s, off);

        if (l == 0) out[e] = s + b2v;
    }
}

// ---------------------------------------------------------------------------
// Inputs (metadata order): z_user f32[100000*128], z_item f32[50000*128],
//   row i32[E], col i32[E], W1 f32[256*128], b1 f32[128], W2 f32[128], b2 f32[1]
// Output: f32[E]
// ---------------------------------------------------------------------------
extern "C" void kernel_launch(void* const* d_in, const int* in_sizes, int n_in,
                              void* d_out, int out_size)
{
    const float* z_user = (const float*)d_in[0];
    const float* z_item = (const float*)d_in[1];
    const int*   row    = (const int*)d_in[2];
    const int*   col    = (const int*)d_in[3];
    const float* W1     = (const float*)d_in[4];
    const float* b1     = (const float*)d_in[5];
    const float* W2     = (const float*)d_in[6];
    const float* b2     = (const float*)d_in[7];
    float* out = (float*)d_out;

    const int n_user = in_sizes[0] / H;
    const int n_item = in_sizes[1] / H;
    const int E      = in_sizes[2];

    const int nb_user = (n_user + 63) / 64;
    const int nb_item = (n_item + 63) / 64;

    precompute_fused<<<nb_user + nb_item, 128>>>(z_user, z_item, W1, b1,
                                                 n_user, n_item, nb_user);

    edge_kernel<<<1184, 256>>>(row, col, W2, b2, out, E);
}